// round 8
// baseline (speedup 1.0000x reference)
#include <cuda_runtime.h>
#include <cuda_bf16.h>
#include <mma.h>
#include <cstdint>

using namespace nvcuda;

// Problem constants
#define BATCH   16
#define NQ      1024
#define NK      1024
#define DIN     512
#define NHEADS  8
#define HDIM    64
#define BN_TOT  (BATCH * NQ)       // 16384
#define NORM_F  0.125f             // 1/sqrt(64)

// -------- scratch (device globals: allocation-free) --------
__device__ float g_Q[(size_t)NHEADS * BN_TOT * HDIM];   // [h][bn][64]
__device__ float g_K[(size_t)NHEADS * BN_TOT * HDIM];
__device__ float g_V[(size_t)NHEADS * BN_TOT * HDIM];
__device__ float g_H[(size_t)BN_TOT * DIN];             // [bn][h*64+v]
__device__ unsigned long long g_Mb[(size_t)BN_TOT * (NK / 64)];  // packed mask bits

__device__ __forceinline__ float f2tf32_rna(float x) {
    uint32_t r;
    asm("cvt.rna.tf32.f32 %0, %1;" : "=r"(r) : "f"(x));
    return __uint_as_float(r);
}

// m16n8k8 tf32 mma (g=lane>>2, t=lane&3):
//   A: a0(g,t) a1(g+8,t) a2(g,t+4) a3(g+8,t+4)
//   B: b0(k=t,n=g) b1(k=t+4,n=g)
//   C: c0(g,2t) c1(g,2t+1) c2(g+8,2t) c3(g+8,2t+1)
__device__ __forceinline__ void mma_tf32(float* c, const uint32_t* a, const uint32_t* b) {
    asm volatile(
        "mma.sync.aligned.m16n8k8.row.col.f32.tf32.tf32.f32 "
        "{%0,%1,%2,%3}, {%4,%5,%6,%7}, {%8,%9}, {%0,%1,%2,%3};"
        : "+f"(c[0]), "+f"(c[1]), "+f"(c[2]), "+f"(c[3])
        : "r"(a[0]), "r"(a[1]), "r"(a[2]), "r"(a[3]), "r"(b[0]), "r"(b[1]));
}

// ============================================================
// Fused QKV projection, exact fp32 SIMT.
// 128x128 tile, 256 threads, 8x8 microtile, BK=16, smem double-buffered
// (1 sync/chunk) + REGISTER double-buffer of operands (hides LDS latency).
// grid = (128 m-tiles, 4 n-tiles, 3 ops)
// ============================================================
#define QBM 128
#define QBN 128
#define QBK 16

__global__ __launch_bounds__(256)
void qkv_proj2(const float* __restrict__ q,
               const float* __restrict__ k,
               const float* __restrict__ v,
               const float* __restrict__ Wq,
               const float* __restrict__ Wk,
               const float* __restrict__ Wv)
{
    __shared__ float Xs[2][QBK][QBM];   // transposed A chunk (k-major)
    __shared__ float Ws[2][QBK][QBN];   // B chunk (row-major)

    const int tid = threadIdx.x;
    const int tx  = tid & 15;    // n dir: 16 x 8 cols
    const int ty  = tid >> 4;    // m dir: 16 x 8 rows
    const int op  = blockIdx.z;
    const int m0  = blockIdx.x * QBM;
    const int n0  = blockIdx.y * QBN;

    const float* X = (op == 0 ? q : (op == 1 ? k : v));
    const float* W = (op == 0 ? Wq : (op == 1 ? Wk : Wv));
    float* Cb      = (op == 0 ? g_Q : (op == 1 ? g_K : g_V));

    const int mA  = tid & 127;
    const int k4a = tid >> 7;                 // 0 or 1; +2 on second iter
    const float* Ag = X + (size_t)(m0 + mA) * DIN;
    const int kkB = tid >> 5;                 // 0..7; +8 on second iter
    const int c4  = tid & 31;
    const float* Bg = W + (size_t)((n0 + c4 * 4) >> 6) * (DIN * HDIM)
                        + ((n0 + c4 * 4) & 63);

    float acc[8][8];
#pragma unroll
    for (int i = 0; i < 8; i++)
#pragma unroll
        for (int j = 0; j < 8; j++) acc[i][j] = 0.f;

    float4 ar[2], br[2];
#pragma unroll
    for (int i = 0; i < 2; ++i) {
        ar[i] = *(const float4*)(Ag + (k4a + 2 * i) * 4);
        br[i] = *(const float4*)(Bg + (size_t)(kkB + 8 * i) * HDIM);
    }
#pragma unroll
    for (int i = 0; i < 2; ++i) {
        int kr = (k4a + 2 * i) * 4;
        Xs[0][kr + 0][mA] = ar[i].x;
        Xs[0][kr + 1][mA] = ar[i].y;
        Xs[0][kr + 2][mA] = ar[i].z;
        Xs[0][kr + 3][mA] = ar[i].w;
        *(float4*)(&Ws[0][kkB + 8 * i][c4 * 4]) = br[i];
    }
    __syncthreads();

    for (int c = 0; c < DIN / QBK; ++c) {
        const int cur = c & 1;
        if (c < DIN / QBK - 1) {
            const int k0n = (c + 1) * QBK;
#pragma unroll
            for (int i = 0; i < 2; ++i) {
                ar[i] = *(const float4*)(Ag + k0n + (k4a + 2 * i) * 4);
                br[i] = *(const float4*)(Bg + (size_t)(k0n + kkB + 8 * i) * HDIM);
            }
        }

        // register double-buffered inner loop
        float a_reg[2][8], b_reg[2][8];
        *(float4*)(a_reg[0])     = *(const float4*)(&Xs[cur][0][ty * 8]);
        *(float4*)(a_reg[0] + 4) = *(const float4*)(&Xs[cur][0][ty * 8 + 4]);
        *(float4*)(b_reg[0])     = *(const float4*)(&Ws[cur][0][tx * 8]);
        *(float4*)(b_reg[0] + 4) = *(const float4*)(&Ws[cur][0][tx * 8 + 4]);
#pragma unroll
        for (int kk = 0; kk < QBK; ++kk) {
            const int cb = kk & 1, nb = cb ^ 1;
            if (kk < QBK - 1) {
                *(float4*)(a_reg[nb])     = *(const float4*)(&Xs[cur][kk + 1][ty * 8]);
                *(float4*)(a_reg[nb] + 4) = *(const float4*)(&Xs[cur][kk + 1][ty * 8 + 4]);
                *(float4*)(b_reg[nb])     = *(const float4*)(&Ws[cur][kk + 1][tx * 8]);
                *(float4*)(b_reg[nb] + 4) = *(const float4*)(&Ws[cur][kk + 1][tx * 8 + 4]);
            }
#pragma unroll
            for (int i = 0; i < 8; i++)
#pragma unroll
                for (int j = 0; j < 8; j++)
                    acc[i][j] = fmaf(a_reg[cb][i], b_reg[cb][j], acc[i][j]);
        }

        if (c < DIN / QBK - 1) {
            const int nxt = cur ^ 1;
#pragma unroll
            for (int i = 0; i < 2; ++i) {
                int kr = (k4a + 2 * i) * 4;
                Xs[nxt][kr + 0][mA] = ar[i].x;
                Xs[nxt][kr + 1][mA] = ar[i].y;
                Xs[nxt][kr + 2][mA] = ar[i].z;
                Xs[nxt][kr + 3][mA] = ar[i].w;
                *(float4*)(&Ws[nxt][kkB + 8 * i][c4 * 4]) = br[i];
            }
            __syncthreads();
        }
    }

    // Epilogue: scatter to per-head layout Cb[h][bn][64].
    const int cgl = n0 + tx * 8;
    const int h   = cgl >> 6;
    const int nh  = cgl & 63;
    float* Crow = Cb + (size_t)h * BN_TOT * HDIM
                     + (size_t)(m0 + ty * 8) * HDIM + nh;
#pragma unroll
    for (int i = 0; i < 8; i++) {
        *(float4*)(Crow + (size_t)i * HDIM)     =
            make_float4(acc[i][0], acc[i][1], acc[i][2], acc[i][3]);
        *(float4*)(Crow + (size_t)i * HDIM + 4) =
            make_float4(acc[i][4], acc[i][5], acc[i][6], acc[i][7]);
    }
}

// ============================================================
// Mask pack: 64 int32 -> 1 uint64 bitmask per (bq, key-tile) via ballot.
// ============================================================
__global__ __launch_bounds__(256)
void pack_mask(const int* __restrict__ mask)
{
    int w = (blockIdx.x * 256 + threadIdx.x) >> 5;
    int lane = threadIdx.x & 31;
    const int* src = mask + (size_t)w * 64;
    unsigned lo = __ballot_sync(0xffffffffu, src[lane] != 0);
    unsigned hi = __ballot_sync(0xffffffffu, src[lane + 32] != 0);
    if (lane == 0)
        g_Mb[w] = ((unsigned long long)hi << 32) | (unsigned long long)lo;
}

// ============================================================
// Out projection: wmma tf32, 128x128 tile, BK=32, double-buffered smem
// (1 sync/chunk). 256 threads = 8 warps (4M x 2N), each warp 32x64 = 2x4
// m16n16k8-frag grid. Dynamic smem: 2*(128*40 + 32*136)*4 = 75776 B.
// grid = (128 m-tiles, 4 n-tiles)
// ============================================================
#define OBK   32
#define OLDA  40    // 32 + 8
#define OLDB  136   // 128 + 8
#define OSM_A (128 * OLDA)
#define OSM_B (OBK * OLDB)
#define OUT_SMEM ((2 * OSM_A + 2 * OSM_B) * 4)

__global__ __launch_bounds__(256)
void out_proj2(const float* __restrict__ A,
               const float* __restrict__ B,
               float* __restrict__ C)
{
    extern __shared__ float osm[];
    float* sA = osm;                    // [2][128][OLDA]
    float* sB = osm + 2 * OSM_A;        // [2][OBK][OLDB]

    const int tid = threadIdx.x;
    const int wid = tid >> 5;
    const int wm  = wid & 3;    // 4 warps in M (32 rows each)
    const int wn  = wid >> 2;   // 2 warps in N (64 cols each)
    const int m0  = blockIdx.x * 128;
    const int n0  = blockIdx.y * 128;

    const float* At = A + (size_t)m0 * DIN;
    const float* Bt = B + n0;

    // staging patterns
    // A: 1024 float4 / chunk; idx = tid + i*256 (i<4): m = idx>>3, c4 = idx&7
    // B: 1024 float4 / chunk; idx = tid + i*256: kk = idx>>5, c4b = idx&31
    const int c4b = tid & 31;

    wmma::fragment<wmma::accumulator, 16, 16, 8, float> acc[2][4];
#pragma unroll
    for (int i = 0; i < 2; i++)
#pragma unroll
        for (int j = 0; j < 4; j++) wmma::fill_fragment(acc[i][j], 0.0f);

    float4 ar[4], br[4];
#pragma unroll
    for (int i = 0; i < 4; ++i) {
        int idx = tid + i * 256;
        ar[i] = *(const float4*)(At + (size_t)(idx >> 3) * DIN + (idx & 7) * 4);
        br[i] = *(const float4*)(Bt + (size_t)(tid >> 5) * DIN + (size_t)(i * 8) * DIN + c4b * 4);
    }
#pragma unroll
    for (int i = 0; i < 4; ++i) {
        int idx = tid + i * 256;
        float4 xv = ar[i];
        xv.x = f2tf32_rna(xv.x); xv.y = f2tf32_rna(xv.y);
        xv.z = f2tf32_rna(xv.z); xv.w = f2tf32_rna(xv.w);
        *(float4*)(sA + (idx >> 3) * OLDA + (idx & 7) * 4) = xv;
        float4 bv = br[i];
        bv.x = f2tf32_rna(bv.x); bv.y = f2tf32_rna(bv.y);
        bv.z = f2tf32_rna(bv.z); bv.w = f2tf32_rna(bv.w);
        *(float4*)(sB + ((tid >> 5) + i * 8) * OLDB + c4b * 4) = bv;
    }
    __syncthreads();

    for (int c = 0; c < DIN / OBK; ++c) {
        const int cur = c & 1;
        const float* sAc = sA + cur * OSM_A;
        const float* sBc = sB + cur * OSM_B;

        if (c < DIN / OBK - 1) {
            const int k0n = (c + 1) * OBK;
#pragma unroll
            for (int i = 0; i < 4; ++i) {
                int idx = tid + i * 256;
                ar[i] = *(const float4*)(At + (size_t)(idx >> 3) * DIN + k0n + (idx & 7) * 4);
                br[i] = *(const float4*)(Bt + (size_t)(k0n + (tid >> 5) + i * 8) * DIN + c4b * 4);
            }
        }

#pragma unroll
        for (int ks = 0; ks < OBK / 8; ++ks) {
            wmma::fragment<wmma::matrix_a, 16, 16, 8, wmma::precision::tf32, wmma::row_major> af[2];
            wmma::fragment<wmma::matrix_b, 16, 16, 8, wmma::precision::tf32, wmma::row_major> bf[4];
#pragma unroll
            for (int i = 0; i < 2; i++)
                wmma::load_matrix_sync(af[i], sAc + (wm * 32 + i * 16) * OLDA + ks * 8, OLDA);
#pragma unroll
            for (int j = 0; j < 4; j++)
                wmma::load_matrix_sync(bf[j], sBc + (ks * 8) * OLDB + wn * 64 + j * 16, OLDB);
#pragma unroll
            for (int i = 0; i < 2; i++)
#pragma unroll
                for (int j = 0; j < 4; j++)
                    wmma::mma_sync(acc[i][j], af[i], bf[j], acc[i][j]);
        }

        if (c < DIN / OBK - 1) {
            const int nxt = cur ^ 1;
#pragma unroll
            for (int i = 0; i < 4; ++i) {
                int idx = tid + i * 256;
                float4 xv = ar[i];
                xv.x = f2tf32_rna(xv.x); xv.y = f2tf32_rna(xv.y);
                xv.z = f2tf32_rna(xv.z); xv.w = f2tf32_rna(xv.w);
                *(float4*)(sA + nxt * OSM_A + (idx >> 3) * OLDA + (idx & 7) * 4) = xv;
                float4 bv = br[i];
                bv.x = f2tf32_rna(bv.x); bv.y = f2tf32_rna(bv.y);
                bv.z = f2tf32_rna(bv.z); bv.w = f2tf32_rna(bv.w);
                *(float4*)(sB + nxt * OSM_B + ((tid >> 5) + i * 8) * OLDB + c4b * 4) = bv;
            }
            __syncthreads();
        }
    }

    float* Ct = C + (size_t)m0 * DIN + n0;
#pragma unroll
    for (int i = 0; i < 2; i++)
#pragma unroll
        for (int j = 0; j < 4; j++)
            wmma::store_matrix_sync(
                Ct + (size_t)(wm * 32 + i * 16) * DIN + wn * 64 + j * 16,
                acc[i][j], DIN, wmma::mem_row_major);
}

// ============================================================
// FA2-style flash attention with raw mma.sync m16n8k8 tf32. (R6, measured good)
// ============================================================
#define LDK 68
#define LDV 72
#define LDP 68
#define ATTN_SMEM ((64 * LDK + 64 * LDV + 128 * LDP) * 4)

__global__ __launch_bounds__(256, 2)
void attn_mma()
{
    extern __shared__ float sm[];
    float* sK = sm;
    float* sV = sK + 64 * LDK;
    float* sP = sV + 64 * LDV;

    const int tid  = threadIdx.x;
    const int w    = tid >> 5;
    const int lane = tid & 31;
    const int g    = lane >> 2;
    const int t    = lane & 3;
    const int q0   = blockIdx.x * 128;
    const int b    = blockIdx.y;
    const int h    = blockIdx.z;

    const float* Qg = g_Q + ((size_t)(h * BATCH + b) * NQ + q0) * HDIM;
    const float* Kg = g_K + (size_t)(h * BATCH + b) * NK * HDIM;
    const float* Vg = g_V + (size_t)(h * BATCH + b) * NK * HDIM;

    uint32_t qf[8][4];
#pragma unroll
    for (int kc = 0; kc < 8; ++kc) {
        const float* r0 = Qg + (size_t)(w * 16 + g) * HDIM + kc * 8;
        const float* r1 = Qg + (size_t)(w * 16 + g + 8) * HDIM + kc * 8;
        qf[kc][0] = __float_as_uint(f2tf32_rna(r0[t] * NORM_F));
        qf[kc][1] = __float_as_uint(f2tf32_rna(r1[t] * NORM_F));
        qf[kc][2] = __float_as_uint(f2tf32_rna(r0[t + 4] * NORM_F));
        qf[kc][3] = __float_as_uint(f2tf32_rna(r1[t + 4] * NORM_F));
    }

    float oacc[8][4];
#pragma unroll
    for (int nt = 0; nt < 8; ++nt)
#pragma unroll
        for (int j = 0; j < 4; ++j) oacc[nt][j] = 0.f;
    float m0 = -1e30f, m1 = -1e30f;
    float l0 = 0.f, l1 = 0.f;

    const unsigned long long* mb_row0 = g_Mb + ((size_t)b * NQ + q0 + w * 16 + g) * (NK / 64);
    const unsigned long long* mb_row1 = mb_row0 + 8 * (NK / 64);
    float* sPw = sP + (w * 16) * LDP;

    for (int kt = 0; kt < NK / 64; ++kt) {
        __syncthreads();
#pragma unroll
        for (int i = 0; i < 4; ++i) {
            int idx = tid + i * 256;
            int r  = idx >> 4;
            int c4 = idx & 15;
            float4 kv = *(const float4*)(Kg + (size_t)(kt * 64 + r) * HDIM + c4 * 4);
            kv.x = f2tf32_rna(kv.x); kv.y = f2tf32_rna(kv.y);
            kv.z = f2tf32_rna(kv.z); kv.w = f2tf32_rna(kv.w);
            *(float4*)(sK + r * LDK + c4 * 4) = kv;
            float4 vv = *(const float4*)(Vg + (size_t)(kt * 64 + r) * HDIM + c4 * 4);
            vv.x = f2tf32_rna(vv.x); vv.y = f2tf32_rna(vv.y);
            vv.z = f2tf32_rna(vv.z); vv.w = f2tf32_rna(vv.w);
            *(float4*)(sV + r * LDV + c4 * 4) = vv;
        }
        __syncthreads();

        float sacc[8][4];
#pragma unroll
        for (int nt = 0; nt < 8; ++nt) {
#pragma unroll
            for (int j = 0; j < 4; ++j) sacc[nt][j] = 0.f;
#pragma unroll
            for (int kc = 0; kc < 8; ++kc) {
                uint32_t bfr[2];
                const float* kb = sK + (nt * 8 + g) * LDK + kc * 8;
                bfr[0] = __float_as_uint(kb[t]);
                bfr[1] = __float_as_uint(kb[t + 4]);
                mma_tf32(sacc[nt], qf[kc], bfr);
            }
        }

        unsigned long long mb0 = mb_row0[kt];
        unsigned long long mb1 = mb_row1[kt];
        float tmax0 = -1e30f, tmax1 = -1e30f;
#pragma unroll
        for (int nt = 0; nt < 8; ++nt) {
            int c0 = nt * 8 + 2 * t, c1 = c0 + 1;
            if ((mb0 >> c0) & 1ull) sacc[nt][0] = -1e30f;
            if ((mb0 >> c1) & 1ull) sacc[nt][1] = -1e30f;
            if ((mb1 >> c0) & 1ull) sacc[nt][2] = -1e30f;
            if ((mb1 >> c1) & 1ull) sacc[nt][3] = -1e30f;
            tmax0 = fmaxf(tmax0, fmaxf(sacc[nt][0], sacc[nt][1]));
            tmax1 = fmaxf(tmax1, fmaxf(sacc[nt][2], sacc[nt][3]));
        }
        tmax0 = fmaxf(tmax0, __shfl_xor_sync(0xffffffffu, tmax0, 1));
        tmax0 = fmaxf(tmax0, __shfl_xor_sync(0xffffffffu, tmax0, 2));
        tmax1 = fmaxf(tmax1, __shfl_xor_sync(0xffffffffu, tmax1, 1));
        tmax1 = fmaxf(tmax1, __shfl_xor_sync(0xffffffffu, tmax1, 2));

        float mn0 = fmaxf(m0, tmax0);
        float mn1 = fmaxf(m1, tmax1);
        float sc0 = __expf(m0 - mn0);
        float sc1 = __expf(m1 - mn1);
        m0 = mn0; m1 = mn1;

        float ps0 = 0.f, ps1 = 0.f;
#pragma unroll
        for (int nt = 0; nt < 8; ++nt) {
            float p0 = __expf(sacc[nt][0] - mn0);
            float p1 = __expf(sacc[nt][1] - mn0);
            float p2 = __expf(sacc[nt][2] - mn1);
            float p3 = __expf(sacc[nt][3] - mn1);
            ps0 += p0 + p1;
            ps1 += p2 + p3;
            float2 lo = make_float2(f2tf32_rna(p0), f2tf32_rna(p1));
            float2 hi = make_float2(f2tf32_rna(p2), f2tf32_rna(p3));
            *(float2*)(sPw + g * LDP + nt * 8 + 2 * t) = lo;
            *(float2*)(sPw + (g + 8) * LDP + nt * 8 + 2 * t) = hi;
        }
        ps0 += __shfl_xor_sync(0xffffffffu, ps0, 1);
        ps0 += __shfl_xor_sync(0xffffffffu, ps0, 2);
        ps1 += __shfl_xor_sync(0xffffffffu, ps1, 1);
        ps1 += __shfl_xor_sync(0xffffffffu, ps1, 2);
        l0 = l0 * sc0 + ps0;
        l1 = l1 * sc1 + ps1;

#pragma unroll
        for (int nt = 0; nt < 8; ++nt) {
            oacc[nt][0] *= sc0; oacc[nt][1] *= sc0;
            oacc[nt][2] *= sc1; oacc[nt][3] *= sc1;
        }
        __syncwarp();

#pragma unroll
        for (int kc = 0; kc < 8; ++kc) {
            uint32_t pa[4];
            const float* p0r = sPw + g * LDP + kc * 8;
            const float* p1r = sPw + (g + 8) * LDP + kc * 8;
            pa[0] = __float_as_uint(p0r[t]);
            pa[1] = __float_as_uint(p1r[t]);
            pa[2] = __float_as_uint(p0r[t + 4]);
            pa[3] = __float_as_uint(p1r[t + 4]);
#pragma unroll
            for (int nt = 0; nt < 8; ++nt) {
                uint32_t bfr[2];
                bfr[0] = __float_as_uint(sV[(kc * 8 + t) * LDV + nt * 8 + g]);
                bfr[1] = __float_as_uint(sV[(kc * 8 + t + 4) * LDV + nt * 8 + g]);
                mma_tf32(oacc[nt], pa, bfr);
            }
        }
        __syncwarp();
    }

    float inv0 = (l0 > 0.f) ? (1.f / l0) : 0.f;
    float inv1 = (l1 > 0.f) ? (1.f / l1) : 0.f;
    float* o0 = g_H + ((size_t)(b * NQ + q0 + w * 16 + g)) * DIN + h * HDIM;
    float* o1 = g_H + ((size_t)(b * NQ + q0 + w * 16 + g + 8)) * DIN + h * HDIM;
#pragma unroll
    for (int nt = 0; nt < 8; ++nt) {
        *(float2*)(o0 + nt * 8 + 2 * t) = make_float2(oacc[nt][0] * inv0, oacc[nt][1] * inv0);
        *(float2*)(o1 + nt * 8 + 2 * t) = make_float2(oacc[nt][2] * inv1, oacc[nt][3] * inv1);
    }
}

// ============================================================
extern "C" void kernel_launch(void* const* d_in, const int* in_sizes, int n_in,
                              void* d_out, int out_size)
{
    const float* q  = (const float*)d_in[0];
    const float* k  = (const float*)d_in[1];
    const float* v  = (const float*)d_in[2];
    const int*   mask = (const int*)d_in[3];
    const float* Wq = (const float*)d_in[4];
    const float* Wk = (const float*)d_in[5];
    const float* Wv = (const float*)d_in[6];
    const float* Wo = (const float*)d_in[7];
    float* out = (float*)d_out;

    float *pH;
    cudaGetSymbolAddress((void**)&pH, g_H);

    static bool attr_set = false;
    if (!attr_set) {
        cudaFuncSetAttribute(attn_mma,
                             cudaFuncAttributeMaxDynamicSharedMemorySize,
                             ATTN_SMEM);
        cudaFuncSetAttribute(out_proj2,
                             cudaFuncAttributeMaxDynamicSharedMemorySize,
                             OUT_SMEM);
        attr_set = true;
    }

    // QKV projections: exact fp32 SIMT, double-buffered smem + regs
    qkv_proj2<<<dim3(BN_TOT / QBM, DIN / QBN, 3), 256>>>(q, k, v, Wq, Wk, Wv);

    // Pack mask to bitmasks
    pack_mask<<<(BN_TOT * (NK / 64)) / 8, 256>>>(mask);

    // Flash attention (raw mma.sync tf32, register softmax)
    attn_mma<<<dim3(NQ / 128, BATCH, NHEADS), 256, ATTN_SMEM>>>();

    // Output projection: wmma tf32, 128x128 double-buffered
    out_proj2<<<dim3(BN_TOT / 128, DIN / 128), 256, OUT_SMEM>>>(pH, Wo, out);
}